// round 12
// baseline (speedup 1.0000x reference)
#include <cuda_runtime.h>
#include <mma.h>
#include <cstdint>

using namespace nvcuda;

#define NT  8192
#define DIM 512
#define HID 2048
#define NE  4
#define BM  128
#define BN  128
#define BK  16

// ---------------- device scratch (no allocs allowed) ----------------
__device__ __align__(16) int   g_cnt[NE];
__device__ __align__(16) int   g_tok[NE * NT];
__device__ __align__(16) int   g_slot[NT * 2];
__device__ __align__(16) float g_gval[NT * 2];
__device__ __align__(16) float g_mid[(size_t)NE * NT * HID];
__device__ __align__(16) float g_y[(size_t)NE * NT * DIM];

// ---------------- reset ----------------
__global__ void reset_kernel() {
    if (threadIdx.x < NE) g_cnt[threadIdx.x] = 0;
}

// ---------------- gating (proven) ----------------
__global__ void gate_kernel(const float* __restrict__ h,
                            const float* __restrict__ wg) {
    int gw   = (blockIdx.x * blockDim.x + threadIdx.x) >> 5;
    int lane = threadIdx.x & 31;
    if (gw >= NT) return;
    const float* hr = h + (size_t)gw * DIM;
    float a0 = 0.f, a1 = 0.f, a2 = 0.f, a3 = 0.f;
    for (int i = lane; i < DIM; i += 32) {
        float  hv = hr[i];
        float4 w  = reinterpret_cast<const float4*>(wg)[i];
        a0 += hv * w.x; a1 += hv * w.y; a2 += hv * w.z; a3 += hv * w.w;
    }
    #pragma unroll
    for (int o = 16; o; o >>= 1) {
        a0 += __shfl_xor_sync(0xffffffffu, a0, o);
        a1 += __shfl_xor_sync(0xffffffffu, a1, o);
        a2 += __shfl_xor_sync(0xffffffffu, a2, o);
        a3 += __shfl_xor_sync(0xffffffffu, a3, o);
    }
    if (lane == 0) {
        float l[4] = {a0, a1, a2, a3};
        int i0 = 0;
        #pragma unroll
        for (int e = 1; e < 4; e++) if (l[e] > l[i0]) i0 = e;
        int i1 = -1;
        #pragma unroll
        for (int e = 0; e < 4; e++)
            if (e != i0 && (i1 < 0 || l[e] > l[i1])) i1 = e;
        float p1  = expf(l[i1] - l[i0]);
        float inv = 1.0f / (1.0f + p1);
        int p = atomicAdd(&g_cnt[i0], 1);
        g_tok[i0 * NT + p] = gw;
        g_slot[gw * 2]     = i0 * NT + p;
        g_gval[gw * 2]     = inv;
        int q = atomicAdd(&g_cnt[i1], 1);
        g_tok[i1 * NT + q] = gw;
        g_slot[gw * 2 + 1] = i1 * NT + q;
        g_gval[gw * 2 + 1] = p1 * inv;
    }
}

// ---------------- wmma tf32 grouped GEMM with hi/lo split ----------------
// D[128,128] = A[128,K] @ B[K,128], A row-major [m][k], B row-major [k][n].
// Split: x = xh + xl (both tf32-representable); D = AhBh + AhBl + AlBh (+ O(2^-22)).
// 8 warps: 4(M) x 2(N); warp tile 32x64 = 2x4 m16n16k8 accumulators.
#define BPITCH 136

template<int KTOT, int NTOT, bool GATHER, bool RELU>
__global__ void __launch_bounds__(256) gemm_kernel(const float* __restrict__ Ain,
                                                   const float* __restrict__ Bg,
                                                   const float* __restrict__ bias) {
    const int e   = blockIdx.z;
    const int cnt = g_cnt[e];
    const int m0  = blockIdx.y * BM;
    if (m0 >= cnt) return;
    const int n0  = blockIdx.x * BN;

    const float* Ag = GATHER ? Ain : g_mid;
    float* outp     = RELU ? g_mid : g_y;

    __shared__ float Ah[BM][BK],  Al[BM][BK];       // 8 KB each
    __shared__ float Bh[BK][BPITCH], Bl[BK][BPITCH];// 8.5 KB each
    __shared__ float Epi[8][256];                   // 8 KB per-warp epilogue buffer

    const int tid  = threadIdx.x;
    const int wid  = tid >> 5;
    const int lane = tid & 31;

    // A loader: row lr = tid>>1, 8 k's at lk (proven R7 map)
    const int lr = tid >> 1, lk = (tid & 1) * 8;
    int arow = m0 + lr; if (arow >= cnt) arow = cnt - 1;
    const float* aptr;
    if (GATHER) aptr = Ag + (size_t)g_tok[e * NT + arow] * KTOT + lk;
    else        aptr = Ag + ((size_t)e * NT + arow) * KTOT + lk;

    // B loader: k-row kb = tid>>4, 8 cols at bc
    const int kb = tid >> 4, bc = (tid & 15) * 8;
    const float* bptr = Bg + (size_t)e * KTOT * NTOT + (size_t)kb * NTOT + n0 + bc;

    // warp tiling
    const int mstrip = (wid >> 1) * 32;
    const int nstrip = (wid & 1) * 64;

    wmma::fragment<wmma::accumulator, 16, 16, 8, float> acc[2][4];
    #pragma unroll
    for (int i = 0; i < 2; i++)
        #pragma unroll
        for (int j = 0; j < 4; j++) wmma::fill_fragment(acc[i][j], 0.0f);

    const int KT = KTOT / BK;

    for (int kt = 0; kt < KT; kt++) {
        // ---- load + split tile kt into smem ----
        {
            const float* ap = aptr + kt * BK;
            float4 v0 = *reinterpret_cast<const float4*>(ap);
            float4 v1 = *reinterpret_cast<const float4*>(ap + 4);
            const float av[8] = {v0.x, v0.y, v0.z, v0.w, v1.x, v1.y, v1.z, v1.w};
            #pragma unroll
            for (int j = 0; j < 8; j++) {
                float hi = wmma::__float_to_tf32(av[j]);
                Ah[lr][lk + j] = hi;
                Al[lr][lk + j] = wmma::__float_to_tf32(av[j] - hi);
            }
            const float* bp = bptr + (size_t)kt * BK * NTOT;
            float4 w0 = *reinterpret_cast<const float4*>(bp);
            float4 w1 = *reinterpret_cast<const float4*>(bp + 4);
            const float bv[8] = {w0.x, w0.y, w0.z, w0.w, w1.x, w1.y, w1.z, w1.w};
            #pragma unroll
            for (int j = 0; j < 8; j++) {
                float hi = wmma::__float_to_tf32(bv[j]);
                Bh[kb][bc + j] = hi;
                Bl[kb][bc + j] = wmma::__float_to_tf32(bv[j] - hi);
            }
        }
        __syncthreads();

        // ---- compute: 2 k8 steps, 3 split terms each ----
        #pragma unroll
        for (int ks = 0; ks < 2; ks++) {
            wmma::fragment<wmma::matrix_a, 16, 16, 8, wmma::precision::tf32, wmma::row_major> ah[2], al[2];
            #pragma unroll
            for (int i = 0; i < 2; i++) {
                wmma::load_matrix_sync(ah[i], &Ah[mstrip + 16 * i][ks * 8], BK);
                wmma::load_matrix_sync(al[i], &Al[mstrip + 16 * i][ks * 8], BK);
            }
            wmma::fragment<wmma::matrix_b, 16, 16, 8, wmma::precision::tf32, wmma::row_major> bh[4], bl[4];
            #pragma unroll
            for (int j = 0; j < 4; j++) {
                wmma::load_matrix_sync(bh[j], &Bh[ks * 8][nstrip + 16 * j], BPITCH);
                wmma::load_matrix_sync(bl[j], &Bl[ks * 8][nstrip + 16 * j], BPITCH);
            }
            #pragma unroll
            for (int i = 0; i < 2; i++)
                #pragma unroll
                for (int j = 0; j < 4; j++) {
                    wmma::mma_sync(acc[i][j], ah[i], bh[j], acc[i][j]);
                    wmma::mma_sync(acc[i][j], ah[i], bl[j], acc[i][j]);
                    wmma::mma_sync(acc[i][j], al[i], bh[j], acc[i][j]);
                }
        }
        __syncthreads();
    }

    // ---- epilogue: per-warp 16x16 staging, bias (+relu), float4 stores ----
    float* epi = &Epi[wid][0];
    const int rr = lane >> 1;            // row within 16x16
    const int cc = (lane & 1) * 8;       // 8 cols
    #pragma unroll
    for (int i = 0; i < 2; i++) {
        #pragma unroll
        for (int j = 0; j < 4; j++) {
            wmma::store_matrix_sync(epi, acc[i][j], 16, wmma::mem_row_major);
            __syncwarp();
            const int r    = m0 + mstrip + 16 * i + rr;
            const int cbase = n0 + nstrip + 16 * j + cc;
            if (r < cnt) {
                float v[8];
                #pragma unroll
                for (int t = 0; t < 8; t++) {
                    v[t] = epi[rr * 16 + cc + t] + bias[(size_t)e * NTOT + cbase + t];
                    if (RELU) v[t] = fmaxf(v[t], 0.f);
                }
                float* orow = outp + ((size_t)e * NT + r) * NTOT + cbase;
                *reinterpret_cast<float4*>(orow)     = make_float4(v[0], v[1], v[2], v[3]);
                *reinterpret_cast<float4*>(orow + 4) = make_float4(v[4], v[5], v[6], v[7]);
            }
            __syncwarp();
        }
    }
}

// ---------------- combine (proven) ----------------
__global__ void combine_kernel(float* __restrict__ out) {
    int idx = blockIdx.x * blockDim.x + threadIdx.x;
    if (idx >= NT * (DIM / 4)) return;
    int n = idx / (DIM / 4);
    int c = idx % (DIM / 4);
    int   sA = g_slot[n * 2],     sB = g_slot[n * 2 + 1];
    float gA = g_gval[n * 2],     gB = g_gval[n * 2 + 1];
    const float4* y4 = reinterpret_cast<const float4*>(g_y);
    float4 a = y4[(size_t)sA * (DIM / 4) + c];
    float4 b = y4[(size_t)sB * (DIM / 4) + c];
    float4 o;
    o.x = gA * a.x + gB * b.x;
    o.y = gA * a.y + gB * b.y;
    o.z = gA * a.z + gB * b.z;
    o.w = gA * a.w + gB * b.w;
    reinterpret_cast<float4*>(out)[idx] = o;
}

// ---------------- launch ----------------
extern "C" void kernel_launch(void* const* d_in, const int* in_sizes, int n_in,
                              void* d_out, int out_size) {
    const float* h  = (const float*)d_in[0];   // [NT, DIM]
    const float* wg = (const float*)d_in[1];   // [DIM, NE]
    const float* w1 = (const float*)d_in[2];   // [NE, DIM, HID] = [e][k][n]
    const float* b1 = (const float*)d_in[3];   // [NE, HID]
    const float* w2 = (const float*)d_in[4];   // [NE, HID, DIM] = [e][k][n]
    const float* b2 = (const float*)d_in[5];   // [NE, DIM]
    float* out = (float*)d_out;                // [NT, DIM]

    reset_kernel<<<1, 32>>>();
    gate_kernel<<<(NT * 32) / 256, 256>>>(h, wg);
    {   // GEMM1: mid = relu(h[tok] @ w1[e] + b1)
        dim3 g(HID / BN, NT / BM, NE);
        gemm_kernel<DIM, HID, true, true><<<g, 256>>>(h, w1, b1);
    }
    {   // GEMM2: y = mid @ w2[e] + b2
        dim3 g(DIM / BN, NT / BM, NE);
        gemm_kernel<HID, DIM, false, false><<<g, 256>>>(h /*unused*/, w2, b2);
    }
    combine_kernel<<<(NT * (DIM / 4) + 255) / 256, 256>>>(out);
}